// round 1
// baseline (speedup 1.0000x reference)
#include <cuda_runtime.h>
#include <math.h>

#define D 1024
#define NH 16
#define HDIM 64
#define NE 64
#define TMAX 16384
#define GH 256   // gate hidden = 4*E

// ---------------- device scratch (no cudaMalloc allowed) ----------------
__device__ float g_k[NE * D];        // k[e, j]  (j = h*64+hd)
__device__ float g_v[NE * D];        // v[e, j]
__device__ float g_A[D * D];         // A[(h,e), d]  folded score weights (incl 1/8)
__device__ float g_sb[D];            // score bias per (h,e)
__device__ float g_MT[D * D];        // MT[dout, (h,e)] folded out-proj weights
__device__ float g_S[TMAX * D];      // scores -> probs (in place)
__device__ float g_AO[TMAX * D];     // attn_out
__device__ float g_Hh[TMAX * GH];    // gate hidden (post-gelu)
__device__ float g_L[TMAX * NE];     // gate logits

// ---------------- precompute kernels (tiny) ----------------

// k,v projections of the 64 expert embeddings. grid = D blocks (one per output
// column j), 64 threads (one per expert).
__global__ void kv_kernel(const float* __restrict__ emb,
                          const float* __restrict__ wk, const float* __restrict__ bk,
                          const float* __restrict__ wv, const float* __restrict__ bv) {
    __shared__ float sk[D];
    __shared__ float sv[D];
    int j = blockIdx.x;
    for (int i = threadIdx.x; i < D / 4; i += 64) {
        ((float4*)sk)[i] = ((const float4*)(wk + (size_t)j * D))[i];
        ((float4*)sv)[i] = ((const float4*)(wv + (size_t)j * D))[i];
    }
    __syncthreads();
    int e = threadIdx.x;
    const float* xe = emb + (size_t)e * D;
    float ak = 0.f, av = 0.f;
#pragma unroll 4
    for (int d = 0; d < D; d++) {
        float xv = xe[d];
        ak = fmaf(xv, sk[d], ak);
        av = fmaf(xv, sv[d], av);
    }
    g_k[e * D + j] = ak + bk[j];
    g_v[e * D + j] = av + bv[j];
}

// A[(h,e), d] = (1/8) * sum_hd Wq[h*64+hd, d] * k[e, h*64+hd]
// sb[(h,e)]   = (1/8) * sum_hd bq[h*64+hd] * k[e, h*64+hd]
__global__ void buildA_kernel(const float* __restrict__ wq, const float* __restrict__ bq) {
    int he = blockIdx.x;
    int h = he >> 6, e = he & 63;
    __shared__ float kk[HDIM];
    if (threadIdx.x < HDIM) kk[threadIdx.x] = g_k[e * D + h * HDIM + threadIdx.x];
    __syncthreads();
    for (int d = threadIdx.x; d < D; d += 256) {
        float acc = 0.f;
#pragma unroll
        for (int hd = 0; hd < HDIM; hd++)
            acc = fmaf(wq[(size_t)(h * HDIM + hd) * D + d], kk[hd], acc);
        g_A[(size_t)he * D + d] = acc * 0.125f;
    }
    if (threadIdx.x == 0) {
        float acc = 0.f;
#pragma unroll
        for (int hd = 0; hd < HDIM; hd++) acc = fmaf(bq[h * HDIM + hd], kk[hd], acc);
        g_sb[he] = acc * 0.125f;
    }
}

// MT[dout, (h,e)] = sum_hd Wo[dout, h*64+hd] * v[e, h*64+hd]
__global__ void buildMT_kernel(const float* __restrict__ wo) {
    int dout = blockIdx.x;
    __shared__ float wrow[D];
    for (int i = threadIdx.x; i < D / 4; i += 256)
        ((float4*)wrow)[i] = ((const float4*)(wo + (size_t)dout * D))[i];
    __syncthreads();
    for (int he = threadIdx.x; he < D; he += 256) {
        int h = he >> 6, e = he & 63;
        const float* vp = g_v + (size_t)e * D + h * HDIM;
        const float* wp = wrow + h * HDIM;
        float acc = 0.f;
#pragma unroll
        for (int hd = 0; hd < HDIM; hd++) acc = fmaf(wp[hd], vp[hd], acc);
        g_MT[(size_t)dout * D + he] = acc;
    }
}

// ---------------- main SGEMM: C[M,N] = A[M,K] * B[N,K]^T + bias, opt GELU -----
// BM=128, BN=128, BK=8, 8x8 per thread, 256 threads, smem double-buffered.
template <int ACT, bool NGUARD>
__global__ __launch_bounds__(256)
void sgemm_kernel(const float* __restrict__ Ag, const float* __restrict__ Bg,
                  const float* __restrict__ bias, float* __restrict__ Cg,
                  int M, int N, int K) {
    constexpr int BM = 128, BN = 128, BK = 8;
    __shared__ float As[2][BK][BM];
    __shared__ float Bs[2][BK][BN];

    const int tid = threadIdx.x;
    const int bm = blockIdx.y * BM;
    const int bn = blockIdx.x * BN;

    const int lrow = tid >> 1;          // 0..127
    const int lcol = (tid & 1) << 2;    // 0 or 4

    const int tx = tid & 15;            // 0..15 -> n
    const int ty = tid >> 4;            // 0..15 -> m

    const float* aptr = Ag + (size_t)(bm + lrow) * K + lcol;
    const float* bptr = Bg + (size_t)(bn + lrow) * K + lcol;
    const bool bvalid = (!NGUARD) || (bn + lrow < N);

    const int ktiles = K / BK;

    // preload tile 0
    {
        float4 ra = *((const float4*)aptr);
        float4 rb = bvalid ? *((const float4*)bptr) : make_float4(0.f, 0.f, 0.f, 0.f);
        As[0][lcol + 0][lrow] = ra.x; As[0][lcol + 1][lrow] = ra.y;
        As[0][lcol + 2][lrow] = ra.z; As[0][lcol + 3][lrow] = ra.w;
        Bs[0][lcol + 0][lrow] = rb.x; Bs[0][lcol + 1][lrow] = rb.y;
        Bs[0][lcol + 2][lrow] = rb.z; Bs[0][lcol + 3][lrow] = rb.w;
    }
    __syncthreads();

    float acc[8][8];
#pragma unroll
    for (int i = 0; i < 8; i++)
#pragma unroll
        for (int j = 0; j < 8; j++) acc[i][j] = 0.f;

    for (int t = 0; t < ktiles; t++) {
        const int cur = t & 1, nxt = cur ^ 1;
        float4 ra, rb;
        const bool have = (t + 1) < ktiles;
        if (have) {
            const float* ap = aptr + (size_t)(t + 1) * BK;
            const float* bp = bptr + (size_t)(t + 1) * BK;
            ra = *((const float4*)ap);
            rb = bvalid ? *((const float4*)bp) : make_float4(0.f, 0.f, 0.f, 0.f);
        }
#pragma unroll
        for (int k = 0; k < BK; k++) {
            float a[8], b[8];
            float4 a0 = *((const float4*)&As[cur][k][ty * 8]);
            float4 a1 = *((const float4*)&As[cur][k][ty * 8 + 4]);
            float4 b0 = *((const float4*)&Bs[cur][k][tx * 8]);
            float4 b1 = *((const float4*)&Bs[cur][k][tx * 8 + 4]);
            a[0]=a0.x;a[1]=a0.y;a[2]=a0.z;a[3]=a0.w;a[4]=a1.x;a[5]=a1.y;a[6]=a1.z;a[7]=a1.w;
            b[0]=b0.x;b[1]=b0.y;b[2]=b0.z;b[3]=b0.w;b[4]=b1.x;b[5]=b1.y;b[6]=b1.z;b[7]=b1.w;
#pragma unroll
            for (int i = 0; i < 8; i++)
#pragma unroll
                for (int j = 0; j < 8; j++)
                    acc[i][j] = fmaf(a[i], b[j], acc[i][j]);
        }
        if (have) {
            As[nxt][lcol + 0][lrow] = ra.x; As[nxt][lcol + 1][lrow] = ra.y;
            As[nxt][lcol + 2][lrow] = ra.z; As[nxt][lcol + 3][lrow] = ra.w;
            Bs[nxt][lcol + 0][lrow] = rb.x; Bs[nxt][lcol + 1][lrow] = rb.y;
            Bs[nxt][lcol + 2][lrow] = rb.z; Bs[nxt][lcol + 3][lrow] = rb.w;
        }
        __syncthreads();
    }

    // epilogue
#pragma unroll
    for (int i = 0; i < 8; i++) {
        int row = bm + ty * 8 + i;
        float* cp = Cg + (size_t)row * N;
#pragma unroll
        for (int j = 0; j < 8; j++) {
            int col = bn + tx * 8 + j;
            if (NGUARD && col >= N) continue;
            float v = acc[i][j];
            if (bias) v += bias[col];
            if (ACT == 1) v = 0.5f * v * (1.0f + erff(v * 0.70710678118654752f));
            cp[col] = v;
        }
    }
}

// ---------------- softmax over groups of 64 (one warp per (t,h)) -------------
__global__ void softmax64_kernel(float* __restrict__ S, int ngroups) {
    int g = blockIdx.x * 8 + (threadIdx.x >> 5);
    int lane = threadIdx.x & 31;
    if (g >= ngroups) return;
    float* p = S + (size_t)g * 64;
    float v0 = p[lane], v1 = p[lane + 32];
    float m = fmaxf(v0, v1);
#pragma unroll
    for (int o = 16; o; o >>= 1) m = fmaxf(m, __shfl_xor_sync(0xffffffffu, m, o));
    float e0 = expf(v0 - m), e1 = expf(v1 - m);
    float s = e0 + e1;
#pragma unroll
    for (int o = 16; o; o >>= 1) s += __shfl_xor_sync(0xffffffffu, s, o);
    float inv = 1.0f / s;
    p[lane] = e0 * inv;
    p[lane + 32] = e1 * inv;
}

// ---------------- top-2 + weights epilogue (one warp per token) --------------
__device__ __forceinline__ bool better(float va, int ia, float vb, int ib) {
    return (va > vb) || (va == vb && ia < ib);
}

__global__ void topk_kernel(const float* __restrict__ L, float* __restrict__ out, int T) {
    int t = blockIdx.x * 8 + (threadIdx.x >> 5);
    int lane = threadIdx.x & 31;
    if (t >= T) return;
    const float* lp = L + (size_t)t * 64;
    float l0 = lp[lane], l1 = lp[lane + 32];
    float m = fmaxf(l0, l1);
#pragma unroll
    for (int o = 16; o; o >>= 1) m = fmaxf(m, __shfl_xor_sync(0xffffffffu, m, o));
    float e0 = expf(l0 - m), e1 = expf(l1 - m);
    float Z = e0 + e1;
#pragma unroll
    for (int o = 16; o; o >>= 1) Z += __shfl_xor_sync(0xffffffffu, Z, o);

    // local sorted top-2 (lane index is always lower than lane+32 -> tie picks l0)
    float v1, v2; int i1, i2;
    if (l1 > l0) { v1 = l1; i1 = lane + 32; v2 = l0; i2 = lane; }
    else         { v1 = l0; i1 = lane;      v2 = l1; i2 = lane + 32; }

#pragma unroll
    for (int o = 16; o; o >>= 1) {
        float w1 = __shfl_xor_sync(0xffffffffu, v1, o);
        int   j1 = __shfl_xor_sync(0xffffffffu, i1, o);
        float w2 = __shfl_xor_sync(0xffffffffu, v2, o);
        int   j2 = __shfl_xor_sync(0xffffffffu, i2, o);
        if (better(w1, j1, v1, i1)) {
            if (better(v1, i1, w2, j2)) { v2 = v1; i2 = i1; }
            else                        { v2 = w2; i2 = j2; }
            v1 = w1; i1 = j1;
        } else {
            if (better(w1, j1, v2, i2)) { v2 = w1; i2 = j1; }
        }
    }

    if (lane == 0) {
        float p1 = expf(v1 - m) / Z;
        float p2 = expf(v2 - m) / Z;
        float denom = p1 + p2 + 1e-8f;
        float w1 = p1 / denom;
        float w2 = p2 / denom;
        out[(size_t)t * 2 + 0] = (float)i1;
        out[(size_t)t * 2 + 1] = (float)i2;
        out[(size_t)2 * T + (size_t)t * 2 + 0] = w1;
        out[(size_t)2 * T + (size_t)t * 2 + 1] = w2;
    }
}

// ---------------- launch ----------------
extern "C" void kernel_launch(void* const* d_in, const int* in_sizes, int n_in,
                              void* d_out, int out_size) {
    const float* x   = (const float*)d_in[0];
    const float* emb = (const float*)d_in[1];
    const float* ipw = (const float*)d_in[2];
    const float* ipb = (const float*)d_in[3];
    const float* opw = (const float*)d_in[4];
    const float* opb = (const float*)d_in[5];
    const float* gw1 = (const float*)d_in[6];
    const float* gb1 = (const float*)d_in[7];
    const float* gw2 = (const float*)d_in[8];
    const float* gb2 = (const float*)d_in[9];

    const int T = in_sizes[0] / D;   // 16384

    float *pA, *psb, *pMT, *pS, *pAO, *pH, *pL;
    cudaGetSymbolAddress((void**)&pA,  g_A);
    cudaGetSymbolAddress((void**)&psb, g_sb);
    cudaGetSymbolAddress((void**)&pMT, g_MT);
    cudaGetSymbolAddress((void**)&pS,  g_S);
    cudaGetSymbolAddress((void**)&pAO, g_AO);
    cudaGetSymbolAddress((void**)&pH,  g_Hh);
    cudaGetSymbolAddress((void**)&pL,  g_L);

    // precompute folded weights
    kv_kernel<<<D, 64>>>(emb, ipw + (size_t)D * D, ipb + D,
                               ipw + (size_t)2 * D * D, ipb + 2 * D);
    buildA_kernel<<<D, 256>>>(ipw, ipb);
    buildMT_kernel<<<D, 256>>>(opw);

    // scores = x @ A^T + sb
    sgemm_kernel<0, false><<<dim3(D / 128, T / 128), 256>>>(x, pA, psb, pS, T, D, D);
    // softmax over each 64-expert group
    softmax64_kernel<<<(T * NH + 7) / 8, 256>>>(pS, T * NH);
    // attn_out = P @ MT^T + b_out
    sgemm_kernel<0, false><<<dim3(D / 128, T / 128), 256>>>(pS, pMT, opb, pAO, T, D, D);
    // h = gelu(attn_out @ W1^T + b1)
    sgemm_kernel<1, false><<<dim3(GH / 128, T / 128), 256>>>(pAO, gw1, gb1, pH, T, GH, D);
    // logits = h @ W2^T + b2   (N=64 < BN=128 -> guarded)
    sgemm_kernel<0, true><<<dim3(1, T / 128), 256>>>(pH, gw2, gb2, pL, T, NE, GH);
    // softmax + top-2 + normalize -> [idx (T*2) | weights (T*2)]
    topk_kernel<<<(T + 7) / 8, 256>>>(pL, (float*)d_out, T);
}

// round 3
// speedup vs baseline: 2.4506x; 2.4506x over previous
#include <cuda_runtime.h>
#include <cuda_fp16.h>
#include <math.h>
#include <stdint.h>

#define D 1024
#define NH 16
#define HDIM 64
#define NE 64
#define TMAX 16384
#define GH 256

// ============================ device scratch ============================
__device__ __align__(16) float g_k[NE * D];
__device__ __align__(16) float g_v[NE * D];
__device__ __align__(16) float g_A[D * D];
__device__ __align__(16) float g_sb[D];
__device__ __align__(16) float g_MT[D * D];
__device__ __align__(16) float g_H[TMAX * GH];
__device__ __align__(16) float g_L[TMAX * NE];

// expanded fp16 operands: A-pattern [hi|hi|lo], B-pattern [hi|lo|hi], width 3K
__device__ __align__(16) __half g_xe[(size_t)TMAX * 3 * D];
__device__ __align__(16) __half g_Pe[(size_t)TMAX * 3 * D];
__device__ __align__(16) __half g_AOe[(size_t)TMAX * 3 * D];
__device__ __align__(16) __half g_Awe[(size_t)D * 3 * D];
__device__ __align__(16) __half g_MTe[(size_t)D * 3 * D];
__device__ __align__(16) __half g_W1e[(size_t)GH * 3 * D];

// ============================ asm helpers ============================
__device__ __forceinline__ uint32_t smem_u32(const void* p) {
    uint32_t a;
    asm("{ .reg .u64 t; cvta.to.shared.u64 t, %1; cvt.u32.u64 %0, t; }" : "=r"(a) : "l"(p));
    return a;
}
__device__ __forceinline__ void cp16(uint32_t dst, const void* src) {
    asm volatile("cp.async.cg.shared.global [%0], [%1], 16;" :: "r"(dst), "l"(src));
}
#define CP_COMMIT() asm volatile("cp.async.commit_group;" ::: "memory")
#define CP_WAIT2() asm volatile("cp.async.wait_group 2;" ::: "memory")

__device__ __forceinline__ void ldsm4(uint32_t& r0, uint32_t& r1, uint32_t& r2, uint32_t& r3,
                                      uint32_t addr) {
    asm volatile("ldmatrix.sync.aligned.m8n8.x4.shared.b16 {%0,%1,%2,%3}, [%4];"
                 : "=r"(r0), "=r"(r1), "=r"(r2), "=r"(r3) : "r"(addr));
}
__device__ __forceinline__ void mma16816(float* c, const uint32_t* a, const uint32_t* b) {
    asm volatile(
        "mma.sync.aligned.m16n8k16.row.col.f32.f16.f16.f32 "
        "{%0,%1,%2,%3}, {%4,%5,%6,%7}, {%8,%9}, {%0,%1,%2,%3};"
        : "+f"(c[0]), "+f"(c[1]), "+f"(c[2]), "+f"(c[3])
        : "r"(a[0]), "r"(a[1]), "r"(a[2]), "r"(a[3]), "r"(b[0]), "r"(b[1]));
}
__device__ __forceinline__ uint32_t packh2(__half a, __half b) {
    __half2 t; t.x = a; t.y = b;
    return *reinterpret_cast<uint32_t*>(&t);
}

// smem swizzle: row stride 64B (32 halves), chunk = 16B unit index 0..3
__device__ __forceinline__ uint32_t swz(uint32_t row, uint32_t chunk) {
    return row * 64u + ((chunk ^ ((row >> 1) & 3u)) * 16u);
}

// ============================ precompute kernels ============================
__global__ void kv_kernel(const float* __restrict__ emb,
                          const float* __restrict__ wk, const float* __restrict__ bk,
                          const float* __restrict__ wv, const float* __restrict__ bv) {
    __shared__ float sk[D];
    __shared__ float sv[D];
    int j = blockIdx.x;
    for (int i = threadIdx.x; i < D / 4; i += 64) {
        ((float4*)sk)[i] = ((const float4*)(wk + (size_t)j * D))[i];
        ((float4*)sv)[i] = ((const float4*)(wv + (size_t)j * D))[i];
    }
    __syncthreads();
    int e = threadIdx.x;
    const float* xe = emb + (size_t)e * D;
    float ak = 0.f, av = 0.f;
#pragma unroll 4
    for (int d = 0; d < D; d++) {
        float xv = xe[d];
        ak = fmaf(xv, sk[d], ak);
        av = fmaf(xv, sv[d], av);
    }
    g_k[e * D + j] = ak + bk[j];
    g_v[e * D + j] = av + bv[j];
}

__global__ void buildA_kernel(const float* __restrict__ wq, const float* __restrict__ bq) {
    int he = blockIdx.x;
    int h = he >> 6, e = he & 63;
    __shared__ float kk[HDIM];
    if (threadIdx.x < HDIM) kk[threadIdx.x] = g_k[e * D + h * HDIM + threadIdx.x];
    __syncthreads();
    for (int d = threadIdx.x; d < D; d += 256) {
        float acc = 0.f;
#pragma unroll
        for (int hd = 0; hd < HDIM; hd++)
            acc = fmaf(wq[(size_t)(h * HDIM + hd) * D + d], kk[hd], acc);
        g_A[(size_t)he * D + d] = acc * 0.125f;
    }
    if (threadIdx.x == 0) {
        float acc = 0.f;
#pragma unroll
        for (int hd = 0; hd < HDIM; hd++) acc = fmaf(bq[h * HDIM + hd], kk[hd], acc);
        g_sb[he] = acc * 0.125f;
    }
}

__global__ void buildMT_kernel(const float* __restrict__ wo) {
    int dout = blockIdx.x;
    __shared__ float wrow[D];
    for (int i = threadIdx.x; i < D / 4; i += 256)
        ((float4*)wrow)[i] = ((const float4*)(wo + (size_t)dout * D))[i];
    __syncthreads();
    for (int he = threadIdx.x; he < D; he += 256) {
        int h = he >> 6, e = he & 63;
        const float* vp = g_v + (size_t)e * D + h * HDIM;
        const float* wp = wrow + h * HDIM;
        float acc = 0.f;
#pragma unroll
        for (int hd = 0; hd < HDIM; hd++) acc = fmaf(wp[hd], vp[hd], acc);
        g_MT[(size_t)dout * D + he] = acc;
    }
}

// ============================ fp32 -> expanded fp16 ============================
template <bool APAT>
__global__ void split_expand(const float* __restrict__ in, __half* __restrict__ out,
                             int K, int n4) {
    int i = blockIdx.x * blockDim.x + threadIdx.x;
    if (i >= n4) return;
    float4 v = ((const float4*)in)[i];
    int base = i * 4;
    int r = base / K, c = base % K;
    __half h0 = __float2half_rn(v.x), h1 = __float2half_rn(v.y);
    __half h2 = __float2half_rn(v.z), h3 = __float2half_rn(v.w);
    __half l0 = __float2half_rn(v.x - __half2float(h0));
    __half l1 = __float2half_rn(v.y - __half2float(h1));
    __half l2 = __float2half_rn(v.z - __half2float(h2));
    __half l3 = __float2half_rn(v.w - __half2float(h3));
    uint2 Hh, Ll;
    Hh.x = packh2(h0, h1); Hh.y = packh2(h2, h3);
    Ll.x = packh2(l0, l1); Ll.y = packh2(l2, l3);
    __half* rp = out + (size_t)r * 3 * K + c;
    *(uint2*)rp = Hh;
    *(uint2*)(rp + K) = APAT ? Hh : Ll;
    *(uint2*)(rp + 2 * K) = APAT ? Ll : Hh;
}

// ============================ HMMA GEMM ============================
// C[M,N] = Ae[M,K'] * Be[N,K']^T (+bias, epilogue).  K' = 3K (emulated fp32).
// EPI 0: +bias -> softmax over 64-col groups -> expanded-A fp16 out (Oe)
// EPI 1: +bias -> expanded-A fp16 out (Oe)
// EPI 2: +bias -> exact gelu -> fp32 out (Of32)
constexpr int BM = 128, BN = 128, BK = 32, STAGES = 4;
constexpr int ASTG = BM * BK * 2;       // 8192 B
constexpr int BSTG = BN * BK * 2;       // 8192 B
constexpr int STG = ASTG + BSTG;        // 16384 B
constexpr int HG_SMEM = STAGES * STG;   // 65536 B

__device__ __forceinline__ void load_stage(uint32_t sbase, const __half* __restrict__ A,
                                           const __half* __restrict__ B,
                                           int bm, int bn, int k0, int Ktot, int tid) {
#pragma unroll
    for (int i = 0; i < 2; i++) {
        int idx = tid + i * 256;
        int row = idx >> 2, c = idx & 3;
        cp16(sbase + swz(row, c), A + (size_t)(bm + row) * Ktot + k0 + c * 8);
    }
#pragma unroll
    for (int i = 0; i < 2; i++) {
        int idx = tid + i * 256;
        int row = idx >> 2, c = idx & 3;
        cp16(sbase + ASTG + swz(row, c), B + (size_t)(bn + row) * Ktot + k0 + c * 8);
    }
}

template <int EPI>
__global__ __launch_bounds__(256, 2)
void hgemm(const __half* __restrict__ Ae, const __half* __restrict__ Be,
           const float* __restrict__ bias,
           __half* __restrict__ Oe, float* __restrict__ Of32,
           int Ktot, int Nout) {
    extern __shared__ char smraw[];
    const uint32_t sbase = smem_u32(smraw);
    const int tid = threadIdx.x;
    const int lane = tid & 31, wid = tid >> 5;
    const int wm = wid & 3, wn = wid >> 2;      // 4 x 2 warp grid
    const int bm = blockIdx.y * BM, bn = blockIdx.x * BN;

    float acc[2][8][4] = {};

    const int KT = Ktot / BK;

#pragma unroll
    for (int s = 0; s < STAGES - 1; s++) {
        load_stage(sbase + s * STG, Ae, Be, bm, bn, s * BK, Ktot, tid);
        CP_COMMIT();
    }

    for (int it = 0; it < KT; it++) {
        CP_WAIT2();
        __syncthreads();
        int nit = it + STAGES - 1;
        if (nit < KT)
            load_stage(sbase + (nit & (STAGES - 1)) * STG, Ae, Be, bm, bn, nit * BK, Ktot, tid);
        CP_COMMIT();

        uint32_t sA = sbase + (it & (STAGES - 1)) * STG;
        uint32_t sB = sA + ASTG;
#pragma unroll
        for (int ks = 0; ks < 2; ks++) {
            uint32_t af[2][4];
#pragma unroll
            for (int mt = 0; mt < 2; mt++) {
                uint32_t row = wm * 32 + mt * 16 + (lane & 15);
                uint32_t ch = ks * 2 + (lane >> 4);
                ldsm4(af[mt][0], af[mt][1], af[mt][2], af[mt][3], sA + swz(row, ch));
            }
            uint32_t bf[4][4];
#pragma unroll
            for (int np = 0; np < 4; np++) {
                uint32_t row = wn * 64 + np * 16 + (lane & 7) + ((lane >> 4) & 1) * 8;
                uint32_t ch = ks * 2 + ((lane >> 3) & 1);
                ldsm4(bf[np][0], bf[np][1], bf[np][2], bf[np][3], sB + swz(row, ch));
            }
#pragma unroll
            for (int mt = 0; mt < 2; mt++)
#pragma unroll
                for (int nt = 0; nt < 8; nt++)
                    mma16816(acc[mt][nt], af[mt], &bf[nt >> 1][(nt & 1) * 2]);
        }
    }

    // ---------------- epilogue ----------------
    const int colb = bn + wn * 64;
    float bv[16];
#pragma unroll
    for (int nt = 0; nt < 8; nt++) {
        int c = colb + nt * 8 + (lane & 3) * 2;
        bv[nt * 2] = bias[c];
        bv[nt * 2 + 1] = bias[c + 1];
    }

#pragma unroll
    for (int mt = 0; mt < 2; mt++) {
#pragma unroll
        for (int h = 0; h < 2; h++) {
            int row = bm + wm * 32 + mt * 16 + (lane >> 2) + h * 8;
            float v[16];
#pragma unroll
            for (int nt = 0; nt < 8; nt++) {
                v[nt * 2] = acc[mt][nt][h * 2] + bv[nt * 2];
                v[nt * 2 + 1] = acc[mt][nt][h * 2 + 1] + bv[nt * 2 + 1];
            }
            if (EPI == 0) {
                float m = v[0];
#pragma unroll
                for (int j = 1; j < 16; j++) m = fmaxf(m, v[j]);
                m = fmaxf(m, __shfl_xor_sync(0xffffffffu, m, 1));
                m = fmaxf(m, __shfl_xor_sync(0xffffffffu, m, 2));
                float s = 0.f;
#pragma unroll
                for (int j = 0; j < 16; j++) { v[j] = expf(v[j] - m); s += v[j]; }
                s += __shfl_xor_sync(0xffffffffu, s, 1);
                s += __shfl_xor_sync(0xffffffffu, s, 2);
                float inv = 1.0f / s;
#pragma unroll
                for (int j = 0; j < 16; j++) v[j] *= inv;
            }
            if (EPI == 2) {
#pragma unroll
                for (int j = 0; j < 16; j++)
                    v[j] = 0.5f * v[j] * (1.0f + erff(v[j] * 0.70710678118654752f));
            }
            if (EPI == 2) {
                float* op = Of32 + (size_t)row * Nout;
#pragma unroll
                for (int nt = 0; nt < 8; nt++) {
                    int c = colb + nt * 8 + (lane & 3) * 2;
                    float2 f2; f2.x = v[nt * 2]; f2.y = v[nt * 2 + 1];
                    *(float2*)(op + c) = f2;
                }
            } else {
                __half* oh = Oe + (size_t)row * 3 * Nout;
#pragma unroll
                for (int nt = 0; nt < 8; nt++) {
                    int c = colb + nt * 8 + (lane & 3) * 2;
                    float a = v[nt * 2], b = v[nt * 2 + 1];
                    __half ha = __float2half_rn(a), hb = __float2half_rn(b);
                    __half la = __float2half_rn(a - __half2float(ha));
                    __half lb = __float2half_rn(b - __half2float(hb));
                    uint32_t Hw = packh2(ha, hb), Lw = packh2(la, lb);
                    *(uint32_t*)(oh + c) = Hw;
                    *(uint32_t*)(oh + Nout + c) = Hw;   // A-pattern duplicate
                    *(uint32_t*)(oh + 2 * Nout + c) = Lw;
                }
            }
        }
    }
}

// ============================ fp32 SGEMM (logits only) ============================
template <int ACT, bool NGUARD>
__global__ __launch_bounds__(256)
void sgemm_kernel(const float* __restrict__ Ag, const float* __restrict__ Bg,
                  const float* __restrict__ bias, float* __restrict__ Cg,
                  int M, int N, int K) {
    constexpr int SBM = 128, SBN = 128, SBK = 8;
    __shared__ float As[2][SBK][SBM];
    __shared__ float Bs[2][SBK][SBN];

    const int tid = threadIdx.x;
    const int bm = blockIdx.y * SBM;
    const int bn = blockIdx.x * SBN;

    const int lrow = tid >> 1;
    const int lcol = (tid & 1) << 2;
    const int tx = tid & 15;
    const int ty = tid >> 4;

    const float* aptr = Ag + (size_t)(bm + lrow) * K + lcol;
    const float* bptr = Bg + (size_t)(bn + lrow) * K + lcol;
    const bool bvalid = (!NGUARD) || (bn + lrow < N);

    const int ktiles = K / SBK;
    {
        float4 ra = *((const float4*)aptr);
        float4 rb = bvalid ? *((const float4*)bptr) : make_float4(0.f, 0.f, 0.f, 0.f);
        As[0][lcol + 0][lrow] = ra.x; As[0][lcol + 1][lrow] = ra.y;
        As[0][lcol + 2][lrow] = ra.z; As[0][lcol + 3][lrow] = ra.w;
        Bs[0][lcol + 0][lrow] = rb.x; Bs[0][lcol + 1][lrow] = rb.y;
        Bs[0][lcol + 2][lrow] = rb.z; Bs[0][lcol + 3][lrow] = rb.w;
    }
    __syncthreads();

    float acc[8][8];
#pragma unroll
    for (int i = 0; i < 8; i++)
#pragma unroll
        for (int j = 0; j < 8; j++) acc[i][j] = 0.f;

    for (int t = 0; t < ktiles; t++) {
        const int cur = t & 1, nxt = cur ^ 1;
        float4 ra, rb;
        const bool have = (t + 1) < ktiles;
        if (have) {
            ra = *((const float4*)(aptr + (size_t)(t + 1) * SBK));
            rb = bvalid ? *((const float4*)(bptr + (size_t)(t + 1) * SBK))
                        : make_float4(0.f, 0.f, 0.f, 0.f);
        }
#pragma unroll
        for (int k = 0; k < SBK; k++) {
            float a[8], b[8];
            float4 a0 = *((const float4*)&As[cur][k][ty * 8]);
            float4 a1 = *((const float4*)&As[cur][k][ty * 8 + 4]);
            float4 b0 = *((const float4*)&Bs[cur][k][tx * 8]);
            float4 b1 = *((const float4*)&Bs[cur][k][tx * 8 + 4]);
            a[0]=a0.x;a[1]=a0.y;a[2]=a0.z;a[3]=a0.w;a[4]=a1.x;a[5]=a1.y;a[6]=a1.z;a[7]=a1.w;
            b[0]=b0.x;b[1]=b0.y;b[2]=b0.z;b[3]=b0.w;b[4]=b1.x;b[5]=b1.y;b[6]=b1.z;b[7]=b1.w;
#pragma unroll
            for (int i = 0; i < 8; i++)
#pragma unroll
                for (int j = 0; j < 8; j++)
                    acc[i][j] = fmaf(a[i], b[j], acc[i][j]);
        }
        if (have) {
            As[nxt][lcol + 0][lrow] = ra.x; As[nxt][lcol + 1][lrow] = ra.y;
            As[nxt][lcol + 2][lrow] = ra.z; As[nxt][lcol + 3][lrow] = ra.w;
            Bs[nxt][lcol + 0][lrow] = rb.x; Bs[nxt][lcol + 1][lrow] = rb.y;
            Bs[nxt][lcol + 2][lrow] = rb.z; Bs[nxt][lcol + 3][lrow] = rb.w;
        }
        __syncthreads();
    }

#pragma unroll
    for (int i = 0; i < 8; i++) {
        int row = bm + ty * 8 + i;
        float* cp = Cg + (size_t)row * N;
#pragma unroll
        for (int j = 0; j < 8; j++) {
            int col = bn + tx * 8 + j;
            if (NGUARD && col >= N) continue;
            float v = acc[i][j];
            if (bias) v += bias[col];
            if (ACT == 1) v = 0.5f * v * (1.0f + erff(v * 0.70710678118654752f));
            cp[col] = v;
        }
    }
}

// ============================ top-2 epilogue ============================
__device__ __forceinline__ bool better(float va, int ia, float vb, int ib) {
    return (va > vb) || (va == vb && ia < ib);
}

__global__ void topk_kernel(const float* __restrict__ L, float* __restrict__ out, int T) {
    int t = blockIdx.x * 8 + (threadIdx.x >> 5);
    int lane = threadIdx.x & 31;
    if (t >= T) return;
    const float* lp = L + (size_t)t * 64;
    float l0 = lp[lane], l1 = lp[lane + 32];
    float m = fmaxf(l0, l1);
#pragma unroll
    for (int o = 16; o; o >>= 1) m = fmaxf(m, __shfl_xor_sync(0xffffffffu, m, o));
    float e0 = expf(l0 - m), e1 = expf(l1 - m);
    float Z = e0 + e1;
#pragma unroll
    for (int o = 16; o; o >>= 1) Z += __shfl_xor_sync(0xffffffffu, Z, o);

    float v1, v2; int i1, i2;
    if (l1 > l0) { v1 = l1; i1 = lane + 32; v2 = l0; i2 = lane; }
    else         { v1 = l0; i1 = lane;      v2 = l1; i2 = lane + 32; }

#pragma unroll
    for (int o = 16; o; o >>= 1) {
        float w1 = __shfl_xor_sync(0xffffffffu, v1, o);
        int   j1 = __shfl_xor_sync(0xffffffffu, i1, o);
        float w2 = __shfl_xor_sync(0xffffffffu, v2, o);
        int   j2 = __shfl_xor_sync(0xffffffffu, i2, o);
        if (better(w1, j1, v1, i1)) {
            if (better(v1, i1, w2, j2)) { v2 = v1; i2 = i1; }
            else                        { v2 = w2; i2 = j2; }
            v1 = w1; i1 = j1;
        } else {
            if (better(w1, j1, v2, i2)) { v2 = w1; i2 = j1; }
        }
    }

    if (lane == 0) {
        float p1 = expf(v1 - m) / Z;
        float p2 = expf(v2 - m) / Z;
        float denom = p1 + p2 + 1e-8f;
        out[(size_t)t * 2 + 0] = (float)i1;
        out[(size_t)t * 2 + 1] = (float)i2;
        out[(size_t)2 * T + (size_t)t * 2 + 0] = p1 / denom;
        out[(size_t)2 * T + (size_t)t * 2 + 1] = p2 / denom;
    }
}

// ============================ launch ============================
extern "C" void kernel_launch(void* const* d_in, const int* in_sizes, int n_in,
                              void* d_out, int out_size) {
    const float* x   = (const float*)d_in[0];
    const float* emb = (const float*)d_in[1];
    const float* ipw = (const float*)d_in[2];
    const float* ipb = (const float*)d_in[3];
    const float* opw = (const float*)d_in[4];
    const float* opb = (const float*)d_in[5];
    const float* gw1 = (const float*)d_in[6];
    const float* gb1 = (const float*)d_in[7];
    const float* gw2 = (const float*)d_in[8];
    const float* gb2 = (const float*)d_in[9];

    const int T = in_sizes[0] / D;

    static bool attr_done = false;
    if (!attr_done) {
        cudaFuncSetAttribute(hgemm<0>, cudaFuncAttributeMaxDynamicSharedMemorySize, HG_SMEM);
        cudaFuncSetAttribute(hgemm<1>, cudaFuncAttributeMaxDynamicSharedMemorySize, HG_SMEM);
        cudaFuncSetAttribute(hgemm<2>, cudaFuncAttributeMaxDynamicSharedMemorySize, HG_SMEM);
        attr_done = true;
    }

    float *pA, *psb, *pMT, *pH, *pL;
    cudaGetSymbolAddress((void**)&pA,  g_A);
    cudaGetSymbolAddress((void**)&psb, g_sb);
    cudaGetSymbolAddress((void**)&pMT, g_MT);
    cudaGetSymbolAddress((void**)&pH,  g_H);
    cudaGetSymbolAddress((void**)&pL,  g_L);
    __half *pxe, *pPe, *pAOe, *pAwe, *pMTe, *pW1e;
    cudaGetSymbolAddress((void**)&pxe,  g_xe);
    cudaGetSymbolAddress((void**)&pPe,  g_Pe);
    cudaGetSymbolAddress((void**)&pAOe, g_AOe);
    cudaGetSymbolAddress((void**)&pAwe, g_Awe);
    cudaGetSymbolAddress((void**)&pMTe, g_MTe);
    cudaGetSymbolAddress((void**)&pW1e, g_W1e);

    // folded weights (fp32)
    kv_kernel<<<D, 64>>>(emb, ipw + (size_t)D * D, ipb + D,
                         ipw + (size_t)2 * D * D, ipb + 2 * D);
    buildA_kernel<<<D, 256>>>(ipw, ipb);
    buildMT_kernel<<<D, 256>>>(opw);

    // expand to fp16 [hi|?|?]
    split_expand<true><<<(T * D / 4 + 255) / 256, 256>>>(x, pxe, D, T * D / 4);
    split_expand<false><<<(D * D / 4 + 255) / 256, 256>>>(pA, pAwe, D, D * D / 4);
    split_expand<false><<<(D * D / 4 + 255) / 256, 256>>>(pMT, pMTe, D, D * D / 4);
    split_expand<false><<<(GH * D / 4 + 255) / 256, 256>>>(gw1, pW1e, D, GH * D / 4);

    const int KE = 3 * D;  // 3072

    // GEMM1: scores = x·A^T + sb -> softmax(64) -> Pe
    hgemm<0><<<dim3(D / BN, T / BM), 256, HG_SMEM>>>(pxe, pAwe, psb, pPe, nullptr, KE, D);
    // GEMM2: AO = P·MT^T + opb -> AOe
    hgemm<1><<<dim3(D / BN, T / BM), 256, HG_SMEM>>>(pPe, pMTe, opb, pAOe, nullptr, KE, D);
    // GEMM3: H = gelu(AO·W1^T + b1) (fp32)
    hgemm<2><<<dim3(GH / BN, T / BM), 256, HG_SMEM>>>(pAOe, pW1e, gb1, nullptr, pH, KE, GH);
    // logits = H·W2^T + b2 (fp32)
    sgemm_kernel<0, true><<<dim3(1, T / 128), 256>>>(pH, gw2, gb2, pL, T, NE, GH);
    // top-2
    topk_kernel<<<(T + 7) / 8, 256>>>(pL, (float*)d_out, T);
}